// round 7
// baseline (speedup 1.0000x reference)
#include <cuda_runtime.h>

// EquivariantLayerNorm: N=262144 rows, DIM = 128 (scalar LN w/ weight+bias)
//                       + 64*3 + 32*5 (segment norms) = 480 fp32.
// HBM-streaming bound (~1.0 GB). R4: kill the result round-trip through shared —
// smem is used for the gather only; results go registers -> gmem directly.

#define S_DIM 128
#define DIM 480
#define ROWS_PER_BLOCK 16
#define THREADS 512
#define EPS 1e-5f

__global__ __launch_bounds__(THREADS) void eqln_kernel(
    const float* __restrict__ x,
    const float* __restrict__ weight,
    const float* __restrict__ bias,
    float* __restrict__ out)
{
    __shared__ float tile[ROWS_PER_BLOCK * DIM];   // 30720 B
    __shared__ float sw[S_DIM];
    __shared__ float sb[S_DIM];

    const int tid = threadIdx.x;
    if (tid < S_DIM) {
        sw[tid] = weight[tid];
        sb[tid] = bias[tid];
    }

    const long long base = (long long)blockIdx.x * (ROWS_PER_BLOCK * DIM);

    // ---- Coalesced vectorized load of 16 rows into shared (streaming hint) ----
    // 16 rows * 480 floats = 1920 float4
    const float4* __restrict__ src4 = reinterpret_cast<const float4*>(x + base);
    float4* t4 = reinterpret_cast<float4*>(tile);
    #pragma unroll
    for (int i = tid; i < ROWS_PER_BLOCK * DIM / 4; i += THREADS)
        t4[i] = __ldcs(src4 + i);
    __syncthreads();

    const int warp = tid >> 5;
    const int lane = tid & 31;
    const float* row = tile + warp * DIM;
    float* __restrict__ orow = out + base + (long long)warp * DIM;

    // ---- Scalar LayerNorm over first 128 elements (1 warp per row) ----
    // Lane owns 4 CONTIGUOUS elements -> one LDS.128 in, one coalesced STG.128 out.
    const float4 v  = *reinterpret_cast<const float4*>(row + 4 * lane);
    float s  = v.x + v.y + v.z + v.w;
    float ss = v.x * v.x + v.y * v.y + v.z * v.z + v.w * v.w;
    #pragma unroll
    for (int o = 16; o > 0; o >>= 1) {
        s  += __shfl_xor_sync(0xFFFFFFFFu, s,  o);
        ss += __shfl_xor_sync(0xFFFFFFFFu, ss, o);
    }
    const float mean = s * (1.0f / 128.0f);
    const float var  = ss * (1.0f / 128.0f) - mean * mean;
    const float inv  = rsqrtf(var + EPS);

    const float4 w4 = *reinterpret_cast<const float4*>(sw + 4 * lane);
    const float4 b4 = *reinterpret_cast<const float4*>(sb + 4 * lane);
    float4 o;
    o.x = (v.x - mean) * inv * w4.x + b4.x;
    o.y = (v.y - mean) * inv * w4.y + b4.y;
    o.z = (v.z - mean) * inv * w4.z + b4.z;
    o.w = (v.w - mean) * inv * w4.w + b4.w;
    __stcs(reinterpret_cast<float4*>(orow + 4 * lane), o);

    // ---- Segment norms: 64 groups of d=3 (offset 128) + 32 groups of d=5 (offset 320) ----
    // Per-lane: 2 groups of d=3, 1 group of d=5 (compile-time split).
    // gcd(3,32)=gcd(5,32)=1 -> conflict-free shared reads. Direct scalar STGs:
    // each warp's stores collectively cover contiguous 384B / 640B spans, so
    // every DRAM sector is fully written.
    #pragma unroll
    for (int gi = 0; gi < 2; gi++) {
        const int g = lane + gi * 32;                  // 0..63
        const float* p = row + S_DIM + 3 * g;
        float* q = orow + S_DIM + 3 * g;
        float a = p[0], b = p[1], c = p[2];
        float m = (a + b + c) * (1.0f / 3.0f);
        float da = a - m, db = b - m, dc = c - m;
        float vr = (da * da + db * db + dc * dc) * (1.0f / 3.0f);
        float iv = rsqrtf(vr + EPS);
        __stcs(q + 0, da * iv);
        __stcs(q + 1, db * iv);
        __stcs(q + 2, dc * iv);
    }
    {
        const float* p = row + S_DIM + 64 * 3 + 5 * lane;
        float* q = orow + S_DIM + 64 * 3 + 5 * lane;
        float a = p[0], b = p[1], c = p[2], d = p[3], e = p[4];
        float m = (a + b + c + d + e) * 0.2f;
        float da = a - m, db = b - m, dc = c - m, dd = d - m, de = e - m;
        float vr = (da * da + db * db + dc * dc + dd * dd + de * de) * 0.2f;
        float iv = rsqrtf(vr + EPS);
        __stcs(q + 0, da * iv);
        __stcs(q + 1, db * iv);
        __stcs(q + 2, dc * iv);
        __stcs(q + 3, dd * iv);
        __stcs(q + 4, de * iv);
    }
}

extern "C" void kernel_launch(void* const* d_in, const int* in_sizes, int n_in,
                              void* d_out, int out_size)
{
    const float* x      = (const float*)d_in[0];
    const float* weight = (const float*)d_in[1];
    const float* bias   = (const float*)d_in[2];
    float* out = (float*)d_out;

    const int n_rows = in_sizes[0] / DIM;            // 262144
    const int grid = n_rows / ROWS_PER_BLOCK;        // 16384

    eqln_kernel<<<grid, THREADS>>>(x, weight, bias, out);
}

// round 9
// speedup vs baseline: 1.1256x; 1.1256x over previous
#include <cuda_runtime.h>

// EquivariantLayerNorm: N=262144 rows, DIM = 128 (scalar LN w/ weight+bias)
//                       + 64*3 + 32*5 (segment norms) = 480 fp32.
// HBM-streaming bound (~1.0 GB).
// R8 == R7 re-bench (R7 hit an infra failure, never ran):
//  - ALL gmem writes are full float4 (R4's scalar STGs fragmented sectors
//    and regressed DRAM 84.2% -> 73.7%).
//  - LN phase: vectorized LDS.128 + direct coalesced STG.128 (no smem
//    round-trip for the first 128 floats of each row).
//  - Segment results: scalar STS in place (conflict-free), then the OWNING
//    WARP copies its 88-float4 row tail after __syncwarp() only -- no
//    second block barrier, warps drain independently.
//  - __ldcs / __stcs streaming hints on full-sector accesses only.

#define S_DIM 128
#define DIM 480
#define ROWS_PER_BLOCK 16
#define THREADS 512
#define EPS 1e-5f

__global__ __launch_bounds__(THREADS) void eqln_kernel(
    const float* __restrict__ x,
    const float* __restrict__ weight,
    const float* __restrict__ bias,
    float* __restrict__ out)
{
    __shared__ float tile[ROWS_PER_BLOCK * DIM];   // 30720 B
    __shared__ float sw[S_DIM];
    __shared__ float sb[S_DIM];

    const int tid = threadIdx.x;
    if (tid < S_DIM) {
        sw[tid] = weight[tid];
        sb[tid] = bias[tid];
    }

    const long long base = (long long)blockIdx.x * (ROWS_PER_BLOCK * DIM);

    // ---- Coalesced vectorized gather of 16 rows into shared ----
    // 16 rows * 480 floats = 1920 float4
    const float4* __restrict__ src4 = reinterpret_cast<const float4*>(x + base);
    float4* t4 = reinterpret_cast<float4*>(tile);
    #pragma unroll
    for (int i = tid; i < ROWS_PER_BLOCK * DIM / 4; i += THREADS)
        t4[i] = __ldcs(src4 + i);
    __syncthreads();

    const int warp = tid >> 5;
    const int lane = tid & 31;
    float* row = tile + warp * DIM;
    float* __restrict__ orow = out + base + (long long)warp * DIM;

    // ---- Scalar LayerNorm over first 128 elements (1 warp per row) ----
    // Lane owns 4 CONTIGUOUS elements: one LDS.128 in, one coalesced STG.128 out.
    const float4 v = *reinterpret_cast<const float4*>(row + 4 * lane);
    float s  = v.x + v.y + v.z + v.w;
    float ss = v.x * v.x + v.y * v.y + v.z * v.z + v.w * v.w;
    #pragma unroll
    for (int o = 16; o > 0; o >>= 1) {
        s  += __shfl_xor_sync(0xFFFFFFFFu, s,  o);
        ss += __shfl_xor_sync(0xFFFFFFFFu, ss, o);
    }
    const float mean = s * (1.0f / 128.0f);
    const float var  = ss * (1.0f / 128.0f) - mean * mean;
    const float inv  = rsqrtf(var + EPS);

    const float4 w4 = *reinterpret_cast<const float4*>(sw + 4 * lane);
    const float4 b4 = *reinterpret_cast<const float4*>(sb + 4 * lane);
    float4 o;
    o.x = (v.x - mean) * inv * w4.x + b4.x;
    o.y = (v.y - mean) * inv * w4.y + b4.y;
    o.z = (v.z - mean) * inv * w4.z + b4.z;
    o.w = (v.w - mean) * inv * w4.w + b4.w;
    __stcs(reinterpret_cast<float4*>(orow + 4 * lane), o);

    // ---- Segment norms: 64 groups of d=3 (offset 128) + 32 groups of d=5 (offset 320) ----
    // Per-lane: 2 groups of d=3, 1 group of d=5. gcd(3,32)=gcd(5,32)=1 ->
    // conflict-free scalar smem access. Results written back IN PLACE in smem.
    #pragma unroll
    for (int gi = 0; gi < 2; gi++) {
        const int g = lane + gi * 32;                  // 0..63
        float* p = row + S_DIM + 3 * g;
        float a = p[0], b = p[1], c = p[2];
        float m = (a + b + c) * (1.0f / 3.0f);
        float da = a - m, db = b - m, dc = c - m;
        float vr = (da * da + db * db + dc * dc) * (1.0f / 3.0f);
        float iv = rsqrtf(vr + EPS);
        p[0] = da * iv;
        p[1] = db * iv;
        p[2] = dc * iv;
    }
    {
        float* p = row + S_DIM + 64 * 3 + 5 * lane;
        float a = p[0], b = p[1], c = p[2], d = p[3], e = p[4];
        float m = (a + b + c + d + e) * 0.2f;
        float da = a - m, db = b - m, dc = c - m, dd = d - m, de = e - m;
        float vr = (da * da + db * db + dc * dc + dd * dd + de * de) * 0.2f;
        float iv = rsqrtf(vr + EPS);
        p[0] = da * iv;
        p[1] = db * iv;
        p[2] = dc * iv;
        p[3] = dd * iv;
        p[4] = de * iv;
    }

    // ---- Per-warp coalesced tail store: floats [128, 480) = 88 float4 ----
    // Same warp wrote these smem locations; only a warp-level sync is needed.
    __syncwarp();
    const float4* __restrict__ tin  = reinterpret_cast<const float4*>(row + S_DIM);
    float4* __restrict__ tout = reinterpret_cast<float4*>(orow + S_DIM);
    const float4 c0 = tin[lane];
    const float4 c1 = tin[lane + 32];
    __stcs(tout + lane,      c0);
    __stcs(tout + lane + 32, c1);
    if (lane < 24) {
        const float4 c2 = tin[lane + 64];
        __stcs(tout + lane + 64, c2);
    }
}

extern "C" void kernel_launch(void* const* d_in, const int* in_sizes, int n_in,
                              void* d_out, int out_size)
{
    const float* x      = (const float*)d_in[0];
    const float* weight = (const float*)d_in[1];
    const float* bias   = (const float*)d_in[2];
    float* out = (float*)d_out;

    const int n_rows = in_sizes[0] / DIM;            // 262144
    const int grid = n_rows / ROWS_PER_BLOCK;        // 16384

    eqln_kernel<<<grid, THREADS>>>(x, weight, bias, out);
}